// round 1
// baseline (speedup 1.0000x reference)
#include <cuda_runtime.h>
#include <math.h>

// ---------------- problem constants ----------------
#define BA    8192      // B*A rows
#define AGN   8         // agents
#define EDIM  64
#define HDIM  512
#define H3    1536
#define NAOUT 16
#define TM    128
#define TN    128
#define TKK   16
#define MAXP  9216      // 8192 + 8*128 padding
#define MTILES (MAXP/TM) // 72

// ---------------- scratch (static device memory; no allocs) ----------------
__device__ float g_wm1[AGN*HDIM*EDIM];
__device__ float g_wm2[AGN*HDIM*HDIM];
__device__ float g_wm3[AGN*HDIM*HDIM];
__device__ float g_wm4[AGN*NAOUT*HDIM];
__device__ float g_xp [MAXP*EDIM];
__device__ float g_hp [MAXP*HDIM];
__device__ float g_y1 [MAXP*HDIM];
__device__ float g_gi [MAXP*H3];
__device__ float g_gh [MAXP*H3];
__device__ float g_hn [MAXP*HDIM];
__device__ float g_q2 [MAXP*HDIM];
__device__ float g_q3 [MAXP*HDIM];
__device__ int   g_perm[MAXP];
__device__ int   g_counts[AGN];
__device__ int   g_cursor[AGN];
__device__ int   g_segstart[AGN];
__device__ int   g_tile_agent[MTILES];

// ---------------- grouping kernels ----------------
__global__ void init_kernel() {
    int i = blockIdx.x * blockDim.x + threadIdx.x;
    if (i < MAXP) g_perm[i] = -1;
    if (i < AGN) { g_counts[i] = 0; g_cursor[i] = 0; }
}

__global__ void count_kernel(const int* __restrict__ ids) {
    int i = blockIdx.x * blockDim.x + threadIdx.x;
    if (i < BA) atomicAdd(&g_counts[ids[i]], 1);
}

__global__ void offsets_kernel() {
    if (threadIdx.x == 0) {
        int off = 0;
        for (int a = 0; a < AGN; a++) {
            g_segstart[a] = off;
            off += ((g_counts[a] + TM - 1) / TM) * TM;
        }
        for (int t = 0; t < MTILES; t++) {
            int r = t * TM;
            int ag = 0;
            for (int a = 1; a < AGN; a++)
                if (r >= g_segstart[a]) ag = a;
            g_tile_agent[t] = ag;
        }
    }
}

__global__ void scatter_kernel(const int* __restrict__ ids) {
    int i = blockIdx.x * blockDim.x + threadIdx.x;
    if (i < BA) {
        int a = ids[i];
        int pos = g_segstart[a] + atomicAdd(&g_cursor[a], 1);
        g_perm[pos] = i;
    }
}

__global__ void gather_kernel(const float* __restrict__ x, const float* __restrict__ h) {
    int pos = blockIdx.x;
    int n = g_perm[pos];
    float4* xp = (float4*)(g_xp + (size_t)pos * EDIM);
    float4* hp = (float4*)(g_hp + (size_t)pos * HDIM);
    if (n >= 0) {
        const float4* xs = (const float4*)(x + (size_t)n * EDIM);
        const float4* hs = (const float4*)(h + (size_t)n * HDIM);
        for (int v = threadIdx.x; v < EDIM/4; v += blockDim.x) xp[v] = xs[v];
        for (int v = threadIdx.x; v < HDIM/4; v += blockDim.x) hp[v] = hs[v];
    } else {
        float4 z = make_float4(0.f, 0.f, 0.f, 0.f);
        for (int v = threadIdx.x; v < EDIM/4; v += blockDim.x) xp[v] = z;
        for (int v = threadIdx.x; v < HDIM/4; v += blockDim.x) hp[v] = z;
    }
}

// ---------------- masked-weight precompute ----------------
// layer: 0=fc1 (O=H,G=E/4), 1=fc2, 2=fc3 (O=H,G=H/4), 3=fc4 (O=NA,G=H/4)
__global__ void mask_kernel(const float* __restrict__ alpha, const float* __restrict__ w,
                            int layer, int O, int G) {
    int idx = blockIdx.x * blockDim.x + threadIdx.x;
    int total = AGN * O * G;
    if (idx >= total) return;
    float* wm = (layer == 0) ? g_wm1 : (layer == 1) ? g_wm2 : (layer == 2) ? g_wm3 : g_wm4;
    int g = idx % G;
    int o = (idx / G) % O;
    int a = idx / (G * O);
    const float* al = alpha + (size_t)idx * 6;
    float l0 = al[0], l1 = al[1], l2 = al[2], l3 = al[3], l4 = al[4], l5 = al[5];
    float mx = fmaxf(fmaxf(fmaxf(l0, l1), fmaxf(l2, l3)), fmaxf(l4, l5));
    float e0 = expf((l0 - mx) * 0.2f);
    float e1 = expf((l1 - mx) * 0.2f);
    float e2 = expf((l2 - mx) * 0.2f);
    float e3 = expf((l3 - mx) * 0.2f);
    float e4 = expf((l4 - mx) * 0.2f);
    float e5 = expf((l5 - mx) * 0.2f);
    float inv = 1.f / (e0 + e1 + e2 + e3 + e4 + e5);
    // PATTERNS columns: k0:{p0,p1,p2} k1:{p0,p3,p4} k2:{p1,p3,p5} k3:{p2,p4,p5}
    float m0 = (e0 + e1 + e2) * inv;
    float m1 = (e0 + e3 + e4) * inv;
    float m2 = (e1 + e3 + e5) * inv;
    float m3 = (e2 + e4 + e5) * inv;
    int I = G * 4;
    const float* wr = w + (size_t)o * I + g * 4;
    float* wo = wm + ((size_t)a * O + o) * I + g * 4;
    wo[0] = wr[0] * m0;
    wo[1] = wr[1] * m1;
    wo[2] = wr[2] * m2;
    wo[3] = wr[3] * m3;
}

// ---------------- tiled fp32 GEMM: Y[m,n] = X[m,:] . W[agent][n,:] + bias ----------------
// xsel: 0=g_xp 1=g_y1 2=g_hp 3=g_hn 4=g_q2
// wsel: 0=g_wm1 1=g_wm2 2=g_wm3  (-1 => Wext, shared weights)
// ysel: 0=g_y1 1=g_gi 2=g_gh 3=g_q2 4=g_q3
__global__ __launch_bounds__(256, 2)
void gemm_kernel(int xsel, const float* __restrict__ Wext, int wsel, long wStride,
                 const float* __restrict__ bias, int ysel, int K, int N, int doRelu) {
    __shared__ float As[TKK][TM];
    __shared__ float Bs[TKK][TN];

    const float* X = (xsel == 0) ? g_xp : (xsel == 1) ? g_y1 : (xsel == 2) ? g_hp
                   : (xsel == 3) ? g_hn : g_q2;
    const float* W = (wsel == 0) ? g_wm1 : (wsel == 1) ? g_wm2 : (wsel == 2) ? g_wm3 : Wext;
    float* Y = (ysel == 0) ? g_y1 : (ysel == 1) ? g_gi : (ysel == 2) ? g_gh
             : (ysel == 3) ? g_q2 : g_q3;

    const int tile_n = blockIdx.x, tile_m = blockIdx.y;
    const int agent = g_tile_agent[tile_m];
    const float* Wb = W + (size_t)agent * wStride;
    const int tid = threadIdx.x;
    const int tx = tid & 15, ty = tid >> 4;
    const int lrow = tid & 127;
    const int lk4 = tid >> 7;  // 0 or 1

    const float* Xg = X + (size_t)(tile_m * TM + lrow) * K + lk4 * 4;
    const float* Wg = Wb + (size_t)(tile_n * TN + lrow) * K + lk4 * 4;

    float acc[8][8];
#pragma unroll
    for (int i = 0; i < 8; i++)
#pragma unroll
        for (int j = 0; j < 8; j++) acc[i][j] = 0.f;

    for (int k0 = 0; k0 < K; k0 += TKK) {
#pragma unroll
        for (int h = 0; h < 2; h++) {
            int kb = lk4 * 4 + h * 8;
            float4 va = *(const float4*)(Xg + k0 + h * 8);
            As[kb + 0][lrow] = va.x;
            As[kb + 1][lrow] = va.y;
            As[kb + 2][lrow] = va.z;
            As[kb + 3][lrow] = va.w;
            float4 vb = *(const float4*)(Wg + k0 + h * 8);
            Bs[kb + 0][lrow] = vb.x;
            Bs[kb + 1][lrow] = vb.y;
            Bs[kb + 2][lrow] = vb.z;
            Bs[kb + 3][lrow] = vb.w;
        }
        __syncthreads();
#pragma unroll
        for (int kk = 0; kk < TKK; kk++) {
            float4 a0 = *(const float4*)&As[kk][ty * 8];
            float4 a1 = *(const float4*)&As[kk][ty * 8 + 4];
            float4 b0 = *(const float4*)&Bs[kk][tx * 8];
            float4 b1 = *(const float4*)&Bs[kk][tx * 8 + 4];
            float av[8] = {a0.x, a0.y, a0.z, a0.w, a1.x, a1.y, a1.z, a1.w};
            float bv[8] = {b0.x, b0.y, b0.z, b0.w, b1.x, b1.y, b1.z, b1.w};
#pragma unroll
            for (int i = 0; i < 8; i++)
#pragma unroll
                for (int j = 0; j < 8; j++)
                    acc[i][j] += av[i] * bv[j];
        }
        __syncthreads();
    }

    const int m0 = tile_m * TM + ty * 8;
    const int n0 = tile_n * TN + tx * 8;
#pragma unroll
    for (int i = 0; i < 8; i++) {
        size_t base = (size_t)(m0 + i) * N + n0;
#pragma unroll
        for (int j = 0; j < 8; j++) {
            float v = acc[i][j] + bias[n0 + j];
            if (doRelu) v = fmaxf(v, 0.f);
            Y[base + j] = v;
        }
    }
}

// ---------------- GRU gate math + scatter of h ----------------
__global__ void gate_kernel(float* __restrict__ out_h) {
    int idx = blockIdx.x * blockDim.x + threadIdx.x;
    if (idx >= MAXP * HDIM) return;
    int pos = idx >> 9;       // / 512
    int j = idx & 511;
    size_t gb = (size_t)pos * H3 + j;
    float ir = g_gi[gb],            hr = g_gh[gb];
    float iz = g_gi[gb + HDIM],     hz = g_gh[gb + HDIM];
    float in_ = g_gi[gb + 2*HDIM],  hn_ = g_gh[gb + 2*HDIM];
    float r = 1.f / (1.f + expf(-(ir + hr)));
    float z = 1.f / (1.f + expf(-(iz + hz)));
    float nn = tanhf(in_ + r * hn_);
    float hprev = g_hp[(size_t)pos * HDIM + j];
    float hv = (1.f - z) * nn + z * hprev;
    g_hn[(size_t)pos * HDIM + j] = hv;
    int n = g_perm[pos];
    if (n >= 0) out_h[(size_t)n * HDIM + j] = hv;
}

// ---------------- fc4 (N=16) + scatter of q ----------------
__global__ void fc4_kernel(const float* __restrict__ b4, float* __restrict__ out_q) {
    int idx = blockIdx.x * blockDim.x + threadIdx.x;
    if (idx >= MAXP * NAOUT) return;
    int pos = idx / NAOUT, o = idx % NAOUT;
    int n = g_perm[pos];
    if (n < 0) return;
    int agent = g_tile_agent[pos / TM];
    const float4* x = (const float4*)(g_q3 + (size_t)pos * HDIM);
    const float4* w = (const float4*)(g_wm4 + ((size_t)agent * NAOUT + o) * HDIM);
    float s = 0.f;
#pragma unroll 8
    for (int k = 0; k < HDIM / 4; k++) {
        float4 xa = x[k], wa = w[k];
        s += xa.x * wa.x + xa.y * wa.y + xa.z * wa.z + xa.w * wa.w;
    }
    out_q[(size_t)n * NAOUT + o] = s + b4[o];
}

// ---------------- launch ----------------
extern "C" void kernel_launch(void* const* d_in, const int* in_sizes, int n_in,
                              void* d_out, int out_size) {
    const float* inputs = (const float*)d_in[0];
    const float* hidden = (const float*)d_in[1];
    const int*   ids    = (const int*)d_in[2];
    const float* fc1_w  = (const float*)d_in[3];
    const float* fc1_b  = (const float*)d_in[4];
    const float* fc1_a  = (const float*)d_in[5];
    const float* w_ih   = (const float*)d_in[6];
    const float* w_hh   = (const float*)d_in[7];
    const float* b_ih   = (const float*)d_in[8];
    const float* b_hh   = (const float*)d_in[9];
    const float* fc2_w  = (const float*)d_in[10];
    const float* fc2_b  = (const float*)d_in[11];
    const float* fc2_a  = (const float*)d_in[12];
    const float* fc3_w  = (const float*)d_in[13];
    const float* fc3_b  = (const float*)d_in[14];
    const float* fc3_a  = (const float*)d_in[15];
    const float* fc4_w  = (const float*)d_in[16];
    const float* fc4_b  = (const float*)d_in[17];
    const float* fc4_a  = (const float*)d_in[18];

    float* out   = (float*)d_out;
    float* out_q = out;                       // [BA, NAOUT]
    float* out_h = out + (size_t)BA * NAOUT;  // [BA, HDIM]

    // 1) agent grouping
    init_kernel<<<(MAXP + 255) / 256, 256>>>();
    count_kernel<<<(BA + 255) / 256, 256>>>(ids);
    offsets_kernel<<<1, 32>>>();
    scatter_kernel<<<(BA + 255) / 256, 256>>>(ids);

    // 2) masked weights (per agent)
    {
        int t1 = AGN * HDIM * (EDIM / 4);
        int t2 = AGN * HDIM * (HDIM / 4);
        int t4 = AGN * NAOUT * (HDIM / 4);
        mask_kernel<<<(t1 + 255) / 256, 256>>>(fc1_a, fc1_w, 0, HDIM, EDIM / 4);
        mask_kernel<<<(t2 + 255) / 256, 256>>>(fc2_a, fc2_w, 1, HDIM, HDIM / 4);
        mask_kernel<<<(t2 + 255) / 256, 256>>>(fc3_a, fc3_w, 2, HDIM, HDIM / 4);
        mask_kernel<<<(t4 + 255) / 256, 256>>>(fc4_a, fc4_w, 3, NAOUT, HDIM / 4);
    }

    // 3) gather permuted activations
    gather_kernel<<<MAXP, 128>>>(inputs, hidden);

    // 4) fc1 + relu : y1 = relu(xp @ wm1[a]^T + b1)
    gemm_kernel<<<dim3(HDIM / TN, MTILES), 256>>>(
        0, nullptr, 0, (long)HDIM * EDIM, fc1_b, 0, EDIM, HDIM, 1);

    // 5) GRU input/ hidden GEMMs (shared weights, stride 0)
    gemm_kernel<<<dim3(H3 / TN, MTILES), 256>>>(
        1, w_ih, -1, 0, b_ih, 1, HDIM, H3, 0);
    gemm_kernel<<<dim3(H3 / TN, MTILES), 256>>>(
        2, w_hh, -1, 0, b_hh, 2, HDIM, H3, 0);

    // 6) GRU gates -> hn (+ scatter h to output)
    gate_kernel<<<(MAXP * HDIM + 255) / 256, 256>>>(out_h);

    // 7) fc2 + relu, fc3 + relu
    gemm_kernel<<<dim3(HDIM / TN, MTILES), 256>>>(
        3, nullptr, 1, (long)HDIM * HDIM, fc2_b, 3, HDIM, HDIM, 1);
    gemm_kernel<<<dim3(HDIM / TN, MTILES), 256>>>(
        4, nullptr, 2, (long)HDIM * HDIM, fc3_b, 4, HDIM, HDIM, 1);

    // 8) fc4 (+ scatter q to output)
    fc4_kernel<<<(MAXP * NAOUT + 255) / 256, 256>>>(fc4_b, out_q);
}

// round 2
// speedup vs baseline: 1.0016x; 1.0016x over previous
#include <cuda_runtime.h>
#include <math.h>

// ---------------- problem constants ----------------
#define BA    8192      // B*A rows
#define AGN   8         // agents
#define EDIM  64
#define HDIM  512
#define H3    1536
#define NAOUT 16
#define TM    128
#define TN    128
#define TKK   16
#define MAXP  9216      // 8192 + 8*128 padding
#define MTILES (MAXP/TM) // 72

// ---------------- scratch (static device memory; no allocs) ----------------
__device__ float g_wm1[AGN*HDIM*EDIM];
__device__ float g_wm2[AGN*HDIM*HDIM];
__device__ float g_wm3[AGN*HDIM*HDIM];
__device__ float g_wm4[AGN*NAOUT*HDIM];
__device__ float g_xp [MAXP*EDIM];
__device__ float g_hp [MAXP*HDIM];
__device__ float g_y1 [MAXP*HDIM];
__device__ float g_gi [MAXP*H3];
__device__ float g_gh [MAXP*H3];
__device__ float g_hn [MAXP*HDIM];
__device__ float g_q2 [MAXP*HDIM];
__device__ float g_q3 [MAXP*HDIM];
__device__ int   g_perm[MAXP];
__device__ int   g_counts[AGN];
__device__ int   g_cursor[AGN];
__device__ int   g_segstart[AGN];
__device__ int   g_tile_agent[MTILES];

// ---------------- grouping kernels ----------------
__global__ void init_kernel() {
    int i = blockIdx.x * blockDim.x + threadIdx.x;
    if (i < MAXP) g_perm[i] = -1;
    if (i < AGN) { g_counts[i] = 0; g_cursor[i] = 0; }
}

__global__ void count_kernel(const int* __restrict__ ids) {
    int i = blockIdx.x * blockDim.x + threadIdx.x;
    if (i < BA) atomicAdd(&g_counts[ids[i]], 1);
}

__global__ void offsets_kernel() {
    if (threadIdx.x == 0) {
        int off = 0;
        for (int a = 0; a < AGN; a++) {
            g_segstart[a] = off;
            off += ((g_counts[a] + TM - 1) / TM) * TM;
        }
        for (int t = 0; t < MTILES; t++) {
            int r = t * TM;
            int ag = 0;
            for (int a = 1; a < AGN; a++)
                if (r >= g_segstart[a]) ag = a;
            g_tile_agent[t] = ag;
        }
    }
}

__global__ void scatter_kernel(const int* __restrict__ ids) {
    int i = blockIdx.x * blockDim.x + threadIdx.x;
    if (i < BA) {
        int a = ids[i];
        int pos = g_segstart[a] + atomicAdd(&g_cursor[a], 1);
        g_perm[pos] = i;
    }
}

__global__ void gather_kernel(const float* __restrict__ x, const float* __restrict__ h) {
    int pos = blockIdx.x;
    int n = g_perm[pos];
    float4* xp = (float4*)(g_xp + (size_t)pos * EDIM);
    float4* hp = (float4*)(g_hp + (size_t)pos * HDIM);
    if (n >= 0) {
        const float4* xs = (const float4*)(x + (size_t)n * EDIM);
        const float4* hs = (const float4*)(h + (size_t)n * HDIM);
        for (int v = threadIdx.x; v < EDIM/4; v += blockDim.x) xp[v] = xs[v];
        for (int v = threadIdx.x; v < HDIM/4; v += blockDim.x) hp[v] = hs[v];
    } else {
        float4 z = make_float4(0.f, 0.f, 0.f, 0.f);
        for (int v = threadIdx.x; v < EDIM/4; v += blockDim.x) xp[v] = z;
        for (int v = threadIdx.x; v < HDIM/4; v += blockDim.x) hp[v] = z;
    }
}

// ---------------- masked-weight precompute ----------------
// layer: 0=fc1 (O=H,G=E/4), 1=fc2, 2=fc3 (O=H,G=H/4), 3=fc4 (O=NA,G=H/4)
__global__ void mask_kernel(const float* __restrict__ alpha, const float* __restrict__ w,
                            int layer, int O, int G) {
    int idx = blockIdx.x * blockDim.x + threadIdx.x;
    int total = AGN * O * G;
    if (idx >= total) return;
    float* wm = (layer == 0) ? g_wm1 : (layer == 1) ? g_wm2 : (layer == 2) ? g_wm3 : g_wm4;
    int g = idx % G;
    int o = (idx / G) % O;
    int a = idx / (G * O);
    const float* al = alpha + (size_t)idx * 6;
    float l0 = al[0], l1 = al[1], l2 = al[2], l3 = al[3], l4 = al[4], l5 = al[5];
    float mx = fmaxf(fmaxf(fmaxf(l0, l1), fmaxf(l2, l3)), fmaxf(l4, l5));
    float e0 = expf((l0 - mx) * 0.2f);
    float e1 = expf((l1 - mx) * 0.2f);
    float e2 = expf((l2 - mx) * 0.2f);
    float e3 = expf((l3 - mx) * 0.2f);
    float e4 = expf((l4 - mx) * 0.2f);
    float e5 = expf((l5 - mx) * 0.2f);
    float inv = 1.f / (e0 + e1 + e2 + e3 + e4 + e5);
    // PATTERNS columns: k0:{p0,p1,p2} k1:{p0,p3,p4} k2:{p1,p3,p5} k3:{p2,p4,p5}
    float m0 = (e0 + e1 + e2) * inv;
    float m1 = (e0 + e3 + e4) * inv;
    float m2 = (e1 + e3 + e5) * inv;
    float m3 = (e2 + e4 + e5) * inv;
    int I = G * 4;
    const float* wr = w + (size_t)o * I + g * 4;
    float* wo = wm + ((size_t)a * O + o) * I + g * 4;
    wo[0] = wr[0] * m0;
    wo[1] = wr[1] * m1;
    wo[2] = wr[2] * m2;
    wo[3] = wr[3] * m3;
}

// ---------------- tiled fp32 GEMM: Y[m,n] = X[m,:] . W[agent][n,:] + bias ----------------
// xsel: 0=g_xp 1=g_y1 2=g_hp 3=g_hn 4=g_q2
// wsel: 0=g_wm1 1=g_wm2 2=g_wm3  (-1 => Wext, shared weights)
// ysel: 0=g_y1 1=g_gi 2=g_gh 3=g_q2 4=g_q3
__global__ __launch_bounds__(256, 2)
void gemm_kernel(int xsel, const float* __restrict__ Wext, int wsel, long wStride,
                 const float* __restrict__ bias, int ysel, int K, int N, int doRelu) {
    __shared__ float As[TKK][TM];
    __shared__ float Bs[TKK][TN];

    const float* X = (xsel == 0) ? g_xp : (xsel == 1) ? g_y1 : (xsel == 2) ? g_hp
                   : (xsel == 3) ? g_hn : g_q2;
    const float* W = (wsel == 0) ? g_wm1 : (wsel == 1) ? g_wm2 : (wsel == 2) ? g_wm3 : Wext;
    float* Y = (ysel == 0) ? g_y1 : (ysel == 1) ? g_gi : (ysel == 2) ? g_gh
             : (ysel == 3) ? g_q2 : g_q3;

    const int tile_n = blockIdx.x, tile_m = blockIdx.y;
    const int agent = g_tile_agent[tile_m];
    const float* Wb = W + (size_t)agent * wStride;
    const int tid = threadIdx.x;
    const int tx = tid & 15, ty = tid >> 4;
    const int lrow = tid & 127;
    const int lk4 = tid >> 7;  // 0 or 1

    const float* Xg = X + (size_t)(tile_m * TM + lrow) * K + lk4 * 4;
    const float* Wg = Wb + (size_t)(tile_n * TN + lrow) * K + lk4 * 4;

    float acc[8][8];
#pragma unroll
    for (int i = 0; i < 8; i++)
#pragma unroll
        for (int j = 0; j < 8; j++) acc[i][j] = 0.f;

    for (int k0 = 0; k0 < K; k0 += TKK) {
#pragma unroll
        for (int h = 0; h < 2; h++) {
            int kb = lk4 * 4 + h * 8;
            float4 va = *(const float4*)(Xg + k0 + h * 8);
            As[kb + 0][lrow] = va.x;
            As[kb + 1][lrow] = va.y;
            As[kb + 2][lrow] = va.z;
            As[kb + 3][lrow] = va.w;
            float4 vb = *(const float4*)(Wg + k0 + h * 8);
            Bs[kb + 0][lrow] = vb.x;
            Bs[kb + 1][lrow] = vb.y;
            Bs[kb + 2][lrow] = vb.z;
            Bs[kb + 3][lrow] = vb.w;
        }
        __syncthreads();
#pragma unroll
        for (int kk = 0; kk < TKK; kk++) {
            float4 a0 = *(const float4*)&As[kk][ty * 8];
            float4 a1 = *(const float4*)&As[kk][ty * 8 + 4];
            float4 b0 = *(const float4*)&Bs[kk][tx * 8];
            float4 b1 = *(const float4*)&Bs[kk][tx * 8 + 4];
            float av[8] = {a0.x, a0.y, a0.z, a0.w, a1.x, a1.y, a1.z, a1.w};
            float bv[8] = {b0.x, b0.y, b0.z, b0.w, b1.x, b1.y, b1.z, b1.w};
#pragma unroll
            for (int i = 0; i < 8; i++)
#pragma unroll
                for (int j = 0; j < 8; j++)
                    acc[i][j] += av[i] * bv[j];
        }
        __syncthreads();
    }

    const int m0 = tile_m * TM + ty * 8;
    const int n0 = tile_n * TN + tx * 8;
#pragma unroll
    for (int i = 0; i < 8; i++) {
        size_t base = (size_t)(m0 + i) * N + n0;
#pragma unroll
        for (int j = 0; j < 8; j++) {
            float v = acc[i][j] + bias[n0 + j];
            if (doRelu) v = fmaxf(v, 0.f);
            Y[base + j] = v;
        }
    }
}

// ---------------- GRU gate math + scatter of h ----------------
__global__ void gate_kernel(float* __restrict__ out_h) {
    int idx = blockIdx.x * blockDim.x + threadIdx.x;
    if (idx >= MAXP * HDIM) return;
    int pos = idx >> 9;       // / 512
    int j = idx & 511;
    size_t gb = (size_t)pos * H3 + j;
    float ir = g_gi[gb],            hr = g_gh[gb];
    float iz = g_gi[gb + HDIM],     hz = g_gh[gb + HDIM];
    float in_ = g_gi[gb + 2*HDIM],  hn_ = g_gh[gb + 2*HDIM];
    float r = 1.f / (1.f + expf(-(ir + hr)));
    float z = 1.f / (1.f + expf(-(iz + hz)));
    float nn = tanhf(in_ + r * hn_);
    float hprev = g_hp[(size_t)pos * HDIM + j];
    float hv = (1.f - z) * nn + z * hprev;
    g_hn[(size_t)pos * HDIM + j] = hv;
    int n = g_perm[pos];
    if (n >= 0) out_h[(size_t)n * HDIM + j] = hv;
}

// ---------------- fc4 (N=16) + scatter of q ----------------
__global__ void fc4_kernel(const float* __restrict__ b4, float* __restrict__ out_q) {
    int idx = blockIdx.x * blockDim.x + threadIdx.x;
    if (idx >= MAXP * NAOUT) return;
    int pos = idx / NAOUT, o = idx % NAOUT;
    int n = g_perm[pos];
    if (n < 0) return;
    int agent = g_tile_agent[pos / TM];
    const float4* x = (const float4*)(g_q3 + (size_t)pos * HDIM);
    const float4* w = (const float4*)(g_wm4 + ((size_t)agent * NAOUT + o) * HDIM);
    float s = 0.f;
#pragma unroll 8
    for (int k = 0; k < HDIM / 4; k++) {
        float4 xa = x[k], wa = w[k];
        s += xa.x * wa.x + xa.y * wa.y + xa.z * wa.z + xa.w * wa.w;
    }
    out_q[(size_t)n * NAOUT + o] = s + b4[o];
}

// ---------------- launch ----------------
extern "C" void kernel_launch(void* const* d_in, const int* in_sizes, int n_in,
                              void* d_out, int out_size) {
    const float* inputs = (const float*)d_in[0];
    const float* hidden = (const float*)d_in[1];
    const int*   ids    = (const int*)d_in[2];
    const float* fc1_w  = (const float*)d_in[3];
    const float* fc1_b  = (const float*)d_in[4];
    const float* fc1_a  = (const float*)d_in[5];
    const float* w_ih   = (const float*)d_in[6];
    const float* w_hh   = (const float*)d_in[7];
    const float* b_ih   = (const float*)d_in[8];
    const float* b_hh   = (const float*)d_in[9];
    const float* fc2_w  = (const float*)d_in[10];
    const float* fc2_b  = (const float*)d_in[11];
    const float* fc2_a  = (const float*)d_in[12];
    const float* fc3_w  = (const float*)d_in[13];
    const float* fc3_b  = (const float*)d_in[14];
    const float* fc3_a  = (const float*)d_in[15];
    const float* fc4_w  = (const float*)d_in[16];
    const float* fc4_b  = (const float*)d_in[17];
    const float* fc4_a  = (const float*)d_in[18];

    float* out   = (float*)d_out;
    float* out_q = out;                       // [BA, NAOUT]
    float* out_h = out + (size_t)BA * NAOUT;  // [BA, HDIM]

    // 1) agent grouping
    init_kernel<<<(MAXP + 255) / 256, 256>>>();
    count_kernel<<<(BA + 255) / 256, 256>>>(ids);
    offsets_kernel<<<1, 32>>>();
    scatter_kernel<<<(BA + 255) / 256, 256>>>(ids);

    // 2) masked weights (per agent)
    {
        int t1 = AGN * HDIM * (EDIM / 4);
        int t2 = AGN * HDIM * (HDIM / 4);
        int t4 = AGN * NAOUT * (HDIM / 4);
        mask_kernel<<<(t1 + 255) / 256, 256>>>(fc1_a, fc1_w, 0, HDIM, EDIM / 4);
        mask_kernel<<<(t2 + 255) / 256, 256>>>(fc2_a, fc2_w, 1, HDIM, HDIM / 4);
        mask_kernel<<<(t2 + 255) / 256, 256>>>(fc3_a, fc3_w, 2, HDIM, HDIM / 4);
        mask_kernel<<<(t4 + 255) / 256, 256>>>(fc4_a, fc4_w, 3, NAOUT, HDIM / 4);
    }

    // 3) gather permuted activations
    gather_kernel<<<MAXP, 128>>>(inputs, hidden);

    // 4) fc1 + relu : y1 = relu(xp @ wm1[a]^T + b1)
    gemm_kernel<<<dim3(HDIM / TN, MTILES), 256>>>(
        0, nullptr, 0, (long)HDIM * EDIM, fc1_b, 0, EDIM, HDIM, 1);

    // 5) GRU input/ hidden GEMMs (shared weights, stride 0)
    gemm_kernel<<<dim3(H3 / TN, MTILES), 256>>>(
        1, w_ih, -1, 0, b_ih, 1, HDIM, H3, 0);
    gemm_kernel<<<dim3(H3 / TN, MTILES), 256>>>(
        2, w_hh, -1, 0, b_hh, 2, HDIM, H3, 0);

    // 6) GRU gates -> hn (+ scatter h to output)
    gate_kernel<<<(MAXP * HDIM + 255) / 256, 256>>>(out_h);

    // 7) fc2 + relu, fc3 + relu
    gemm_kernel<<<dim3(HDIM / TN, MTILES), 256>>>(
        3, nullptr, 1, (long)HDIM * HDIM, fc2_b, 3, HDIM, HDIM, 1);
    gemm_kernel<<<dim3(HDIM / TN, MTILES), 256>>>(
        4, nullptr, 2, (long)HDIM * HDIM, fc3_b, 4, HDIM, HDIM, 1);

    // 8) fc4 (+ scatter q to output)
    fc4_kernel<<<(MAXP * NAOUT + 255) / 256, 256>>>(fc4_b, out_q);
}